// round 14
// baseline (speedup 1.0000x reference)
#include <cuda_runtime.h>
#include <cstdint>

// Embedding gather with 256-bit global accesses (sm_103a: LDG.E.256/STG.E.256).
// x: [32768] int32; emb: [50257, 512] f32; out: [32768, 512] f32.
// even ids -> id 0 (reference: jnp.where(x % 2 == 0, 0, x)).
//
// Same bytes as the 14.4us plateau kernels, HALF the L1tex instructions:
// 4x ld.global.nc.v8.f32 + 4x st.global.v8.f32 per thread instead of
// 8x LDG.128 + 8x STG.128. Tests whether the plateau is per-instruction
// L1tex processing (expect ~2x headroom) or per-byte (expect neutral).
//
// 512 threads/CTA, 32 rows/CTA. Row = 64 x 32B units.
// Chunk c (c=0..3) covers rows 8c..8c+7: thread group g=tid>>6 owns row
// 8c+g, col unit = tid&63. g is warp-uniform -> broadcast id loads.

static constexpr int ROWS_PER_BLOCK = 32;
static constexpr int THREADS        = 512;
static constexpr int FLOATS_PER_ROW = 512;

struct V8 { float f[8]; };

__device__ __forceinline__ V8 ldg256(const float* p) {
    V8 v;
    asm volatile("ld.global.nc.v8.f32 {%0,%1,%2,%3,%4,%5,%6,%7}, [%8];"
                 : "=f"(v.f[0]), "=f"(v.f[1]), "=f"(v.f[2]), "=f"(v.f[3]),
                   "=f"(v.f[4]), "=f"(v.f[5]), "=f"(v.f[6]), "=f"(v.f[7])
                 : "l"(p));
    return v;
}

__device__ __forceinline__ void stg256(float* p, const V8& v) {
    asm volatile("st.global.v8.f32 [%0], {%1,%2,%3,%4,%5,%6,%7,%8};"
                 :: "l"(p),
                    "f"(v.f[0]), "f"(v.f[1]), "f"(v.f[2]), "f"(v.f[3]),
                    "f"(v.f[4]), "f"(v.f[5]), "f"(v.f[6]), "f"(v.f[7])
                 : "memory");
}

__global__ __launch_bounds__(THREADS)
void embed_gather_kernel(const int* __restrict__ x,
                         const float* __restrict__ emb,
                         float* __restrict__ out) {
    const int base = blockIdx.x * ROWS_PER_BLOCK;
    const int tid  = threadIdx.x;

    const int g   = tid >> 6;        // 0..7, warp-uniform row group
    const int col = tid & 63;        // 32B unit within the row

    // Warp-uniform broadcast id loads for the 4 chunks.
    const int* xb = x + base + g;
    int t0 = __ldg(xb +  0);
    int t1 = __ldg(xb +  8);
    int t2 = __ldg(xb + 16);
    int t3 = __ldg(xb + 24);

    t0 = (t0 & 1) ? t0 : 0;          // even ids -> row 0
    t1 = (t1 & 1) ? t1 : 0;
    t2 = (t2 & 1) ? t2 : 0;
    t3 = (t3 & 1) ? t3 : 0;

    const float* ec = emb + (size_t)col * 8;
    V8 v0 = ldg256(ec + (size_t)t0 * FLOATS_PER_ROW);
    V8 v1 = ldg256(ec + (size_t)t1 * FLOATS_PER_ROW);
    V8 v2 = ldg256(ec + (size_t)t2 * FLOATS_PER_ROW);
    V8 v3 = ldg256(ec + (size_t)t3 * FLOATS_PER_ROW);

    // Store: chunk c writes flat 32B-unit index c*512 + tid of the CTA tile.
    float* dst = out + (size_t)base * FLOATS_PER_ROW + (size_t)tid * 8;
    stg256(dst + 0 * THREADS * 8, v0);
    stg256(dst + 1 * THREADS * 8, v1);
    stg256(dst + 2 * THREADS * 8, v2);
    stg256(dst + 3 * THREADS * 8, v3);
}

extern "C" void kernel_launch(void* const* d_in, const int* in_sizes, int n_in,
                              void* d_out, int out_size) {
    const int* x     = (const int*)d_in[0];
    const float* emb = (const float*)d_in[1];
    float* out       = (float*)d_out;

    int n_rows   = in_sizes[0];                 // 32768 (multiple of 32)
    int n_blocks = n_rows / ROWS_PER_BLOCK;     // 1024

    embed_gather_kernel<<<n_blocks, THREADS>>>(x, emb, out);
}